// round 8
// baseline (speedup 1.0000x reference)
#include <cuda_runtime.h>
#include <math.h>

#define NB 4096
#define NS 64
#define NY 256
#define NH 128
#define NE 32
#define NKG 8
#define NKA 20
#define NNC 50
#define NNT 5

typedef unsigned long long ull;

__device__ __forceinline__ float sigmoidf_(float v) { return 1.f / (1.f + expf(-v)); }

#define FMA2(acc, a, b) asm("fma.rn.f32x2 %0, %1, %2, %0;" : "+l"(acc) : "l"(a), "l"(b))
#define PACK2(o, lo, hi) asm("mov.b64 %0, {%1, %2};" : "=l"(o) : "f"(lo), "f"(hi))
#define UNPACK2(lo, hi, in) asm("mov.b64 {%0, %1}, %2;" : "=f"(lo), "=f"(hi) : "l"(in))
#define FMAX4(m, v) do { \
    m.x = fmaxf(m.x, v.x); m.y = fmaxf(m.y, v.y); \
    m.z = fmaxf(m.z, v.z); m.w = fmaxf(m.w, v.w); } while (0)

// one 4-K step of a 4-row column GEMM, f32x2
#define GSTEP(W, STRIDE, CC, XB, RS, I, ACC) do {                               \
    float _w0 = (W)[((I) + 0) * (STRIDE) + (CC)];                               \
    float _w1 = (W)[((I) + 1) * (STRIDE) + (CC)];                               \
    float _w2 = (W)[((I) + 2) * (STRIDE) + (CC)];                               \
    float _w3 = (W)[((I) + 3) * (STRIDE) + (CC)];                               \
    ull _wa, _wb; PACK2(_wa, _w0, _w1); PACK2(_wb, _w2, _w3);                   \
    _Pragma("unroll")                                                           \
    for (int _j = 0; _j < 4; _j++) {                                            \
        ulonglong2 _x = *reinterpret_cast<const ulonglong2*>(                   \
            &(XB)[_j * (RS) + (I)]);                                            \
        FMA2((ACC)[_j], _x.x, _wa);                                             \
        FMA2((ACC)[_j], _x.y, _wb);                                             \
    } } while (0)

__device__ __forceinline__ void head_sel(int c,
    const float* W_country, const float* W_type, const float* W_taste,
    const float* W_grape, const float* W_aroma,
    const float** Wp, int* stride, int* cc)
{
    if (c < NNC)       { *Wp = W_country; *stride = NNC; *cc = c; }
    else if (c == NNC) { *Wp = W_type;    *stride = 1;   *cc = 0; }
    else if (c < 56)   { *Wp = W_taste;   *stride = NNT; *cc = c - 51; }
    else if (c < 88)   { *Wp = W_grape;   *stride = NE;  *cc = c - 56; }
    else if (c < 120)  { *Wp = W_aroma;   *stride = NE;  *cc = c - 88; }
    else               { *Wp = W_country; *stride = NNC; *cc = 0; }   // dummy lanes
}

// 16 rows per block = 4 pipelined groups of 4; 256 threads; grid 256; 3 blocks/SM.
__global__ __launch_bounds__(256, 3) void wine_fused(
    const float4* __restrict__ x4,
    const int*   __restrict__ grapes,
    const float* __restrict__ grapes_scales,
    const int*   __restrict__ aromas,
    const float* __restrict__ aromas_scales,
    const float* __restrict__ W_common, const float* __restrict__ b_common,
    const float* __restrict__ W_country, const float* __restrict__ b_country,
    const float* __restrict__ W_type,   const float* __restrict__ b_type,
    const float* __restrict__ W_taste,  const float* __restrict__ b_taste,
    const float* __restrict__ W_aroma,  const float* __restrict__ b_aroma,
    const float* __restrict__ W_grape,  const float* __restrict__ b_grape,
    const float* __restrict__ grapes_emb,
    const float* __restrict__ aroma_emb,
    float* __restrict__ out)
{
    __shared__ __align__(16) float xs[2][4 * NY];   // 8 KB ping-pong
    __shared__ __align__(16) float ys[2][4 * NH];   // 4 KB ping-pong
    __shared__ float red [2][128][5];               // 5 KB
    __shared__ float redH[2][128][5];               // 5 KB
    __shared__ __align__(16) float yg_sm[16 * NE];  // 2 KB
    __shared__ __align__(16) float ya_sm[16 * NE];  // 2 KB

    const int tid = threadIdx.x;
    const int b0  = blockIdx.x * 16;
    const int h   = tid & 127;
    const int kq  = tid >> 7;
    const int sr  = tid >> 6;        // stream row within group (0..3)
    const int sc  = tid & 63;        // stream float4-col (0..63)
    const float NEGINF = __int_as_float(0xff800000);

    const float* Wp; int hstride, hcc;
    head_sel(h, W_country, W_type, W_taste, W_grape, W_aroma, &Wp, &hstride, &hcc);

#define REDUCE_Y(YB) do {                                                      \
    float bb = b_common[tid];                                                  \
    _Pragma("unroll")                                                          \
    for (int j = 0; j < 4; j++) {                                              \
        float v = red[0][tid][j] + red[1][tid][j] + bb;                        \
        (YB)[j * NH + tid] = (v > 0.f) ? v : expm1f(v);                        \
    } } while (0)

#define FIN_HEADS(C, GB, GL) do {                                              \
    float s_[4];                                                               \
    _Pragma("unroll")                                                          \
    for (int j = 0; j < 4; j++) s_[j] = redH[0][C][j] + redH[1][C][j];         \
    if ((C) < NNC) {                                                           \
        float bb = b_country[C];                                               \
        _Pragma("unroll")                                                      \
        for (int j = 0; j < 4; j++)                                            \
            out[(size_t)((GB) + j) * NNC + (C)] = s_[j] + bb;                  \
    } else if ((C) == NNC) {                                                   \
        float bb = b_type[0];                                                  \
        _Pragma("unroll")                                                      \
        for (int j = 0; j < 4; j++)                                            \
            out[(size_t)NB * NNC + ((GB) + j)] = sigmoidf_(s_[j] + bb);        \
    } else if ((C) < 56) {                                                     \
        int cc_ = (C) - 51; float bb = b_taste[cc_];                           \
        _Pragma("unroll")                                                      \
        for (int j = 0; j < 4; j++)                                            \
            out[(size_t)NB * 51 + (size_t)((GB) + j) * NNT + cc_] =            \
                sigmoidf_(s_[j] + bb);                                         \
    } else if ((C) < 88) {                                                     \
        int e_ = (C) - 56; float bb = b_grape[e_];                             \
        _Pragma("unroll")                                                      \
        for (int j = 0; j < 4; j++) yg_sm[((GL) + j) * NE + e_] = s_[j] + bb;  \
    } else {                                                                   \
        int e_ = (C) - 88; float bb = b_aroma[e_];                             \
        _Pragma("unroll")                                                      \
        for (int j = 0; j < 4; j++) ya_sm[((GL) + j) * NE + e_] = s_[j] + bb;  \
    } } while (0)

#define STORE_MAX(XB) do {                                                     \
    float4 rr;                                                                 \
    rr.x = fmaxf(fmaxf(m0.x, m1.x), fmaxf(m2.x, m3.x));                        \
    rr.y = fmaxf(fmaxf(m0.y, m1.y), fmaxf(m2.y, m3.y));                        \
    rr.z = fmaxf(fmaxf(m0.z, m1.z), fmaxf(m2.z, m3.z));                        \
    rr.w = fmaxf(fmaxf(m0.w, m1.w), fmaxf(m2.w, m3.w));                        \
    reinterpret_cast<float4*>(XB)[sr * (NY / 4) + sc] = rr; } while (0)

    // ================= P0: stream g0 -> xs[0] =================
    {
        const float4* p = x4 + (size_t)(b0 + sr) * (NS * NY / 4) + sc;
        float4 m0 = p[0], m1 = p[64], m2 = p[128], m3 = p[192];
        #pragma unroll
        for (int s = 4; s < NS; s += 4) {
            float4 v0 = p[(s + 0) * 64], v1 = p[(s + 1) * 64];
            float4 v2 = p[(s + 2) * 64], v3 = p[(s + 3) * 64];
            FMAX4(m0, v0); FMAX4(m1, v1); FMAX4(m2, v2); FMAX4(m3, v3);
        }
        STORE_MAX(xs[0]);
    }
    __syncthreads();

    // ================= P1: GEMM1(g0) + stream g1 -> xs[1] =================
    {
        const int kb = kq * 128;
        const float4* p = x4 + (size_t)(b0 + 4 + sr) * (NS * NY / 4) + sc;
        float4 m0 = make_float4(NEGINF, NEGINF, NEGINF, NEGINF);
        float4 m1 = m0, m2 = m0, m3 = m0;
        ull acc[4] = {0ull, 0ull, 0ull, 0ull};
        #pragma unroll 2
        for (int it = 0; it < 16; it++) {
            float4 v0 = p[(4 * it + 0) * 64], v1 = p[(4 * it + 1) * 64];
            float4 v2 = p[(4 * it + 2) * 64], v3 = p[(4 * it + 3) * 64];
            GSTEP(W_common, NH, h, xs[0], NY, kb + 8 * it,     acc);
            GSTEP(W_common, NH, h, xs[0], NY, kb + 8 * it + 4, acc);
            FMAX4(m0, v0); FMAX4(m1, v1); FMAX4(m2, v2); FMAX4(m3, v3);
        }
        #pragma unroll
        for (int j = 0; j < 4; j++) {
            float lo, hi; UNPACK2(lo, hi, acc[j]);
            red[kq][h][j] = lo + hi;
        }
        STORE_MAX(xs[1]);
    }
    __syncthreads();
    if (tid < 128) REDUCE_Y(ys[0]);          // y(g0)
    __syncthreads();

    // ======= P2: GEMM1(g1) + heads(g0) + stream g2 -> xs[0] =======
    {
        const int kb = kq * 128, kbH = kq * 64;
        const float4* p = x4 + (size_t)(b0 + 8 + sr) * (NS * NY / 4) + sc;
        float4 m0 = make_float4(NEGINF, NEGINF, NEGINF, NEGINF);
        float4 m1 = m0, m2 = m0, m3 = m0;
        ull accg[4] = {0ull, 0ull, 0ull, 0ull};
        ull acch[4] = {0ull, 0ull, 0ull, 0ull};
        #pragma unroll 2
        for (int it = 0; it < 16; it++) {
            float4 v0 = p[(4 * it + 0) * 64], v1 = p[(4 * it + 1) * 64];
            float4 v2 = p[(4 * it + 2) * 64], v3 = p[(4 * it + 3) * 64];
            GSTEP(W_common, NH, h,     xs[0 + 1], NY, kb + 8 * it,     accg);
            GSTEP(Wp, hstride, hcc,    ys[0],     NH, kbH + 4 * it,    acch);
            GSTEP(W_common, NH, h,     xs[0 + 1], NY, kb + 8 * it + 4, accg);
            FMAX4(m0, v0); FMAX4(m1, v1); FMAX4(m2, v2); FMAX4(m3, v3);
        }
        #pragma unroll
        for (int j = 0; j < 4; j++) {
            float lo, hi; UNPACK2(lo, hi, accg[j]);
            red[kq][h][j] = lo + hi;
        }
        if (h < 120) {
            #pragma unroll
            for (int j = 0; j < 4; j++) {
                float lo, hi; UNPACK2(lo, hi, acch[j]);
                redH[kq][h][j] = lo + hi;
            }
        }
        STORE_MAX(xs[0]);
    }
    __syncthreads();
    if (tid < 128) { REDUCE_Y(ys[1]); }      // y(g1)
    else if (tid < 248) { const int c = tid - 128; FIN_HEADS(c, b0, 0); }
    __syncthreads();

    // ======= P3: GEMM1(g2) + heads(g1) + stream g3 -> xs[1] =======
    {
        const int kb = kq * 128, kbH = kq * 64;
        const float4* p = x4 + (size_t)(b0 + 12 + sr) * (NS * NY / 4) + sc;
        float4 m0 = make_float4(NEGINF, NEGINF, NEGINF, NEGINF);
        float4 m1 = m0, m2 = m0, m3 = m0;
        ull accg[4] = {0ull, 0ull, 0ull, 0ull};
        ull acch[4] = {0ull, 0ull, 0ull, 0ull};
        #pragma unroll 2
        for (int it = 0; it < 16; it++) {
            float4 v0 = p[(4 * it + 0) * 64], v1 = p[(4 * it + 1) * 64];
            float4 v2 = p[(4 * it + 2) * 64], v3 = p[(4 * it + 3) * 64];
            GSTEP(W_common, NH, h,  xs[0], NY, kb + 8 * it,     accg);
            GSTEP(Wp, hstride, hcc, ys[1], NH, kbH + 4 * it,    acch);
            GSTEP(W_common, NH, h,  xs[0], NY, kb + 8 * it + 4, accg);
            FMAX4(m0, v0); FMAX4(m1, v1); FMAX4(m2, v2); FMAX4(m3, v3);
        }
        #pragma unroll
        for (int j = 0; j < 4; j++) {
            float lo, hi; UNPACK2(lo, hi, accg[j]);
            red[kq][h][j] = lo + hi;
        }
        if (h < 120) {
            #pragma unroll
            for (int j = 0; j < 4; j++) {
                float lo, hi; UNPACK2(lo, hi, acch[j]);
                redH[kq][h][j] = lo + hi;
            }
        }
        STORE_MAX(xs[1]);
    }
    __syncthreads();
    if (tid < 128) { REDUCE_Y(ys[0]); }      // y(g2)
    else if (tid < 248) { const int c = tid - 128; FIN_HEADS(c, b0 + 4, 4); }
    __syncthreads();

    // ======= P4: GEMM1(g3) + heads(g2) (no stream left) =======
    {
        const int kb = kq * 128, kbH = kq * 64;
        ull accg[4] = {0ull, 0ull, 0ull, 0ull};
        ull acch[4] = {0ull, 0ull, 0ull, 0ull};
        #pragma unroll 2
        for (int it = 0; it < 16; it++) {
            GSTEP(W_common, NH, h,  xs[1], NY, kb + 8 * it,     accg);
            GSTEP(Wp, hstride, hcc, ys[0], NH, kbH + 4 * it,    acch);
            GSTEP(W_common, NH, h,  xs[1], NY, kb + 8 * it + 4, accg);
        }
        #pragma unroll
        for (int j = 0; j < 4; j++) {
            float lo, hi; UNPACK2(lo, hi, accg[j]);
            red[kq][h][j] = lo + hi;
        }
        if (h < 120) {
            #pragma unroll
            for (int j = 0; j < 4; j++) {
                float lo, hi; UNPACK2(lo, hi, acch[j]);
                redH[kq][h][j] = lo + hi;
            }
        }
    }
    __syncthreads();
    if (tid < 128) { REDUCE_Y(ys[1]); }      // y(g3)
    else if (tid < 248) { const int c = tid - 128; FIN_HEADS(c, b0 + 8, 8); }
    __syncthreads();

    // ======= P5: heads(g3) =======
    {
        const int kbH = kq * 64;
        ull acch[4] = {0ull, 0ull, 0ull, 0ull};
        #pragma unroll 4
        for (int it = 0; it < 16; it++)
            GSTEP(Wp, hstride, hcc, ys[1], NH, kbH + 4 * it, acch);
        if (h < 120) {
            #pragma unroll
            for (int j = 0; j < 4; j++) {
                float lo, hi; UNPACK2(lo, hi, acch[j]);
                redH[kq][h][j] = lo + hi;
            }
        }
    }
    __syncthreads();
    if (tid < 120) { FIN_HEADS(tid, b0 + 12, 12); }
    __syncthreads();

    // ======= P6: ragged scoring, all 16 rows =======
    if (tid < 128) {                          // 16 rows x 8 grape slots
        const int r = tid >> 3, k = tid & 7;
        const int b = b0 + r;
        const int   idx = grapes[b * NKG + k];
        const float sc2 = grapes_scales[b * NKG + k];
        const float4* emb = reinterpret_cast<const float4*>(grapes_emb) + (size_t)idx * (NE / 4);
        const float4* yv4 = reinterpret_cast<const float4*>(&yg_sm[r * NE]);
        float acc = 0.f;
        #pragma unroll
        for (int i = 0; i < NE / 4; i++) {
            float4 ev = emb[i], yv = yv4[i];
            acc += ev.x * yv.x + ev.y * yv.y + ev.z * yv.z + ev.w * yv.w;
        }
        float mask = (idx != 0) ? 1.f : 0.f;
        out[(size_t)NB * 56 + (size_t)b * NKG + k] = sigmoidf_(acc) * mask;
        out[(size_t)NB * 64 + (size_t)b * NKG + k] = sc2;
    }
    for (int task = tid; task < 16 * NKA; task += 256) {   // 16 rows x 20 aroma slots
        const int r = task / NKA, k = task % NKA;
        const int b = b0 + r;
        const int   idx = aromas[b * NKA + k];
        const float sc2 = aromas_scales[b * NKA + k];
        const float4* emb = reinterpret_cast<const float4*>(aroma_emb) + (size_t)idx * (NE / 4);
        const float4* yv4 = reinterpret_cast<const float4*>(&ya_sm[r * NE]);
        float acc = 0.f;
        #pragma unroll
        for (int i = 0; i < NE / 4; i++) {
            float4 ev = emb[i], yv = yv4[i];
            acc += ev.x * yv.x + ev.y * yv.y + ev.z * yv.z + ev.w * yv.w;
        }
        float mask = (sc2 != 0.f) ? 1.f : 0.f;
        out[(size_t)NB * 72 + (size_t)b * NKA + k] = sigmoidf_(acc) * mask;
        out[(size_t)NB * 92 + (size_t)b * NKA + k] = sc2;
    }
#undef REDUCE_Y
#undef FIN_HEADS
#undef STORE_MAX
}

extern "C" void kernel_launch(void* const* d_in, const int* in_sizes, int n_in,
                              void* d_out, int out_size) {
    const float* x_enc          = (const float*)d_in[0];
    const int*   grapes         = (const int*)  d_in[1];
    const float* grapes_scales  = (const float*)d_in[2];
    const int*   aromas         = (const int*)  d_in[3];
    const float* aromas_scales  = (const float*)d_in[4];
    const float* W_common       = (const float*)d_in[5];
    const float* b_common       = (const float*)d_in[6];
    const float* W_country      = (const float*)d_in[7];
    const float* b_country      = (const float*)d_in[8];
    const float* W_type         = (const float*)d_in[9];
    const float* b_type         = (const float*)d_in[10];
    const float* W_taste        = (const float*)d_in[11];
    const float* b_taste        = (const float*)d_in[12];
    const float* W_aroma        = (const float*)d_in[13];
    const float* b_aroma        = (const float*)d_in[14];
    const float* W_grape        = (const float*)d_in[15];
    const float* b_grape        = (const float*)d_in[16];
    const float* grapes_emb     = (const float*)d_in[17];
    const float* aroma_emb      = (const float*)d_in[18];
    float* out = (float*)d_out;

    wine_fused<<<NB / 16, 256>>>(reinterpret_cast<const float4*>(x_enc),
                                 grapes, grapes_scales, aromas, aromas_scales,
                                 W_common, b_common, W_country, b_country,
                                 W_type, b_type, W_taste, b_taste,
                                 W_aroma, b_aroma, W_grape, b_grape,
                                 grapes_emb, aroma_emb, out);
}

// round 9
// speedup vs baseline: 1.3212x; 1.3212x over previous
#include <cuda_runtime.h>
#include <math.h>

#define NB 4096
#define NS 64
#define NY 256
#define NH 128
#define NE 32
#define NKG 8
#define NKA 20
#define NNC 50
#define NNT 5

typedef unsigned long long ull;

__device__ __forceinline__ float sigmoidf_(float v) { return 1.f / (1.f + expf(-v)); }

#define FMA2(acc, a, b) asm("fma.rn.f32x2 %0, %1, %2, %0;" : "+l"(acc) : "l"(a), "l"(b))
#define PACK2(o, lo, hi) asm("mov.b64 %0, {%1, %2};" : "=l"(o) : "f"(lo), "f"(hi))
#define UNPACK2(lo, hi, in) asm("mov.b64 {%0, %1}, %2;" : "=f"(lo), "=f"(hi) : "l"(in))
#define FMAX4(m, v) do { \
    m.x = fmaxf(m.x, v.x); m.y = fmaxf(m.y, v.y); \
    m.z = fmaxf(m.z, v.z); m.w = fmaxf(m.w, v.w); } while (0)

// one 4-K step of a 4-row column GEMM, f32x2
#define GSTEP(W, STRIDE, CC, XB, RS, I, ACC) do {                               \
    float _w0 = (W)[((I) + 0) * (STRIDE) + (CC)];                               \
    float _w1 = (W)[((I) + 1) * (STRIDE) + (CC)];                               \
    float _w2 = (W)[((I) + 2) * (STRIDE) + (CC)];                               \
    float _w3 = (W)[((I) + 3) * (STRIDE) + (CC)];                               \
    ull _wa, _wb; PACK2(_wa, _w0, _w1); PACK2(_wb, _w2, _w3);                   \
    _Pragma("unroll")                                                           \
    for (int _j = 0; _j < 4; _j++) {                                            \
        ulonglong2 _x = *reinterpret_cast<const ulonglong2*>(                   \
            &(XB)[_j * (RS) + (I)]);                                            \
        FMA2((ACC)[_j], _x.x, _wa);                                             \
        FMA2((ACC)[_j], _x.y, _wb);                                             \
    } } while (0)

__device__ __forceinline__ void head_sel(int c,
    const float* W_country, const float* W_type, const float* W_taste,
    const float* W_grape, const float* W_aroma,
    const float** Wp, int* stride, int* cc)
{
    if (c < NNC)       { *Wp = W_country; *stride = NNC; *cc = c; }
    else if (c == NNC) { *Wp = W_type;    *stride = 1;   *cc = 0; }
    else if (c < 56)   { *Wp = W_taste;   *stride = NNT; *cc = c - 51; }
    else if (c < 88)   { *Wp = W_grape;   *stride = NE;  *cc = c - 56; }
    else if (c < 120)  { *Wp = W_aroma;   *stride = NE;  *cc = c - 88; }
    else               { *Wp = W_country; *stride = NNC; *cc = 0; }   // dummy lanes
}

// 8 rows per block = 2 pipelined groups of 4; 256 threads; grid 512; 4 blocks/SM.
__global__ __launch_bounds__(256, 4) void wine_fused(
    const float4* __restrict__ x4,
    const int*   __restrict__ grapes,
    const float* __restrict__ grapes_scales,
    const int*   __restrict__ aromas,
    const float* __restrict__ aromas_scales,
    const float* __restrict__ W_common, const float* __restrict__ b_common,
    const float* __restrict__ W_country, const float* __restrict__ b_country,
    const float* __restrict__ W_type,   const float* __restrict__ b_type,
    const float* __restrict__ W_taste,  const float* __restrict__ b_taste,
    const float* __restrict__ W_aroma,  const float* __restrict__ b_aroma,
    const float* __restrict__ W_grape,  const float* __restrict__ b_grape,
    const float* __restrict__ grapes_emb,
    const float* __restrict__ aroma_emb,
    float* __restrict__ out)
{
    __shared__ __align__(16) float xs[2][4 * NY];   // 8 KB ping-pong
    __shared__ __align__(16) float ys[2][4 * NH];   // 4 KB ping-pong
    __shared__ float red [2][128][5];               // 5 KB
    __shared__ float redH[2][128][5];               // 5 KB
    __shared__ __align__(16) float yg_sm[8 * NE];   // 1 KB
    __shared__ __align__(16) float ya_sm[8 * NE];   // 1 KB

    const int tid = threadIdx.x;
    const int b0  = blockIdx.x * 8;
    const int h   = tid & 127;
    const int kq  = tid >> 7;
    const int sr  = tid >> 6;        // stream row within 4-row group
    const int sc  = tid & 63;        // stream float4-col
    const float NEGINF = __int_as_float(0xff800000);

    const float* Wp; int hstride, hcc;
    head_sel(h, W_country, W_type, W_taste, W_grape, W_aroma, &Wp, &hstride, &hcc);

#define REDUCE_Y(YB) do {                                                      \
    float bb = b_common[tid];                                                  \
    _Pragma("unroll")                                                          \
    for (int j = 0; j < 4; j++) {                                              \
        float v = red[0][tid][j] + red[1][tid][j] + bb;                        \
        (YB)[j * NH + tid] = (v > 0.f) ? v : expm1f(v);                        \
    } } while (0)

#define FIN_HEADS(C, GB, GL) do {                                              \
    float s_[4];                                                               \
    _Pragma("unroll")                                                          \
    for (int j = 0; j < 4; j++) s_[j] = redH[0][C][j] + redH[1][C][j];         \
    if ((C) < NNC) {                                                           \
        float bb = b_country[C];                                               \
        _Pragma("unroll")                                                      \
        for (int j = 0; j < 4; j++)                                            \
            out[(size_t)((GB) + j) * NNC + (C)] = s_[j] + bb;                  \
    } else if ((C) == NNC) {                                                   \
        float bb = b_type[0];                                                  \
        _Pragma("unroll")                                                      \
        for (int j = 0; j < 4; j++)                                            \
            out[(size_t)NB * NNC + ((GB) + j)] = sigmoidf_(s_[j] + bb);        \
    } else if ((C) < 56) {                                                     \
        int cc_ = (C) - 51; float bb = b_taste[cc_];                           \
        _Pragma("unroll")                                                      \
        for (int j = 0; j < 4; j++)                                            \
            out[(size_t)NB * 51 + (size_t)((GB) + j) * NNT + cc_] =            \
                sigmoidf_(s_[j] + bb);                                         \
    } else if ((C) < 88) {                                                     \
        int e_ = (C) - 56; float bb = b_grape[e_];                             \
        _Pragma("unroll")                                                      \
        for (int j = 0; j < 4; j++) yg_sm[((GL) + j) * NE + e_] = s_[j] + bb;  \
    } else {                                                                   \
        int e_ = (C) - 88; float bb = b_aroma[e_];                             \
        _Pragma("unroll")                                                      \
        for (int j = 0; j < 4; j++) ya_sm[((GL) + j) * NE + e_] = s_[j] + bb;  \
    } } while (0)

    // ================= P0: stream g0 (rows b0..b0+3) -> xs[0] =================
    {
        const float4* p = x4 + (size_t)(b0 + sr) * (NS * NY / 4) + sc;
        float4 m0 = p[0], m1 = p[64], m2 = p[128], m3 = p[192];
        #pragma unroll
        for (int s = 4; s < NS; s += 4) {
            float4 v0 = p[(s + 0) * 64], v1 = p[(s + 1) * 64];
            float4 v2 = p[(s + 2) * 64], v3 = p[(s + 3) * 64];
            FMAX4(m0, v0); FMAX4(m1, v1); FMAX4(m2, v2); FMAX4(m3, v3);
        }
        float4 rr;
        rr.x = fmaxf(fmaxf(m0.x, m1.x), fmaxf(m2.x, m3.x));
        rr.y = fmaxf(fmaxf(m0.y, m1.y), fmaxf(m2.y, m3.y));
        rr.z = fmaxf(fmaxf(m0.z, m1.z), fmaxf(m2.z, m3.z));
        rr.w = fmaxf(fmaxf(m0.w, m1.w), fmaxf(m2.w, m3.w));
        reinterpret_cast<float4*>(xs[0])[sr * (NY / 4) + sc] = rr;
    }
    __syncthreads();

    // ========== P1: GEMM1(g0) + stream g1 (rows b0+4..b0+7) -> xs[1] ==========
    {
        const int kb = kq * 128;
        const float4* p = x4 + (size_t)(b0 + 4 + sr) * (NS * NY / 4) + sc;
        float4 ma = make_float4(NEGINF, NEGINF, NEGINF, NEGINF);
        float4 mb = ma;
        ull acc[4] = {0ull, 0ull, 0ull, 0ull};
        #pragma unroll 4
        for (int it = 0; it < 32; it++) {
            float4 v0 = p[(2 * it + 0) * 64];
            float4 v1 = p[(2 * it + 1) * 64];
            GSTEP(W_common, NH, h, xs[0], NY, kb + 4 * it, acc);
            FMAX4(ma, v0); FMAX4(mb, v1);
        }
        #pragma unroll
        for (int j = 0; j < 4; j++) {
            float lo, hi; UNPACK2(lo, hi, acc[j]);
            red[kq][h][j] = lo + hi;
        }
        float4 rr;
        rr.x = fmaxf(ma.x, mb.x); rr.y = fmaxf(ma.y, mb.y);
        rr.z = fmaxf(ma.z, mb.z); rr.w = fmaxf(ma.w, mb.w);
        reinterpret_cast<float4*>(xs[1])[sr * (NY / 4) + sc] = rr;
    }
    __syncthreads();
    if (tid < 128) REDUCE_Y(ys[0]);          // y(g0)
    __syncthreads();

    // ========== P2: GEMM1(g1) + heads(g0) ==========
    {
        const int kb = kq * 128, kbH = kq * 64;
        ull accg[4] = {0ull, 0ull, 0ull, 0ull};
        ull acch[4] = {0ull, 0ull, 0ull, 0ull};
        #pragma unroll 2
        for (int it = 0; it < 16; it++) {
            GSTEP(W_common, NH, h,  xs[1], NY, kb + 8 * it,     accg);
            GSTEP(Wp, hstride, hcc, ys[0], NH, kbH + 4 * it,    acch);
            GSTEP(W_common, NH, h,  xs[1], NY, kb + 8 * it + 4, accg);
        }
        #pragma unroll
        for (int j = 0; j < 4; j++) {
            float lo, hi; UNPACK2(lo, hi, accg[j]);
            red[kq][h][j] = lo + hi;
        }
        if (h < 120) {
            #pragma unroll
            for (int j = 0; j < 4; j++) {
                float lo, hi; UNPACK2(lo, hi, acch[j]);
                redH[kq][h][j] = lo + hi;
            }
        }
    }
    __syncthreads();
    if (tid < 128) { REDUCE_Y(ys[1]); }      // y(g1)
    else if (tid < 248) { const int c = tid - 128; FIN_HEADS(c, b0, 0); }
    __syncthreads();

    // ========== P3: heads(g1) ==========
    {
        const int kbH = kq * 64;
        ull acch[4] = {0ull, 0ull, 0ull, 0ull};
        #pragma unroll 4
        for (int it = 0; it < 16; it++)
            GSTEP(Wp, hstride, hcc, ys[1], NH, kbH + 4 * it, acch);
        if (h < 120) {
            #pragma unroll
            for (int j = 0; j < 4; j++) {
                float lo, hi; UNPACK2(lo, hi, acch[j]);
                redH[kq][h][j] = lo + hi;
            }
        }
    }
    __syncthreads();
    if (tid < 120) { FIN_HEADS(tid, b0 + 4, 4); }
    __syncthreads();

    // ========== P4: ragged scoring, all 8 rows ==========
    if (tid < 64) {                           // 8 rows x 8 grape slots
        const int r = tid >> 3, k = tid & 7;
        const int b = b0 + r;
        const int   idx = grapes[b * NKG + k];
        const float sc2 = grapes_scales[b * NKG + k];
        const float4* emb = reinterpret_cast<const float4*>(grapes_emb) + (size_t)idx * (NE / 4);
        const float4* yv4 = reinterpret_cast<const float4*>(&yg_sm[r * NE]);
        float acc = 0.f;
        #pragma unroll
        for (int i = 0; i < NE / 4; i++) {
            float4 ev = emb[i], yv = yv4[i];
            acc += ev.x * yv.x + ev.y * yv.y + ev.z * yv.z + ev.w * yv.w;
        }
        float mask = (idx != 0) ? 1.f : 0.f;
        out[(size_t)NB * 56 + (size_t)b * NKG + k] = sigmoidf_(acc) * mask;
        out[(size_t)NB * 64 + (size_t)b * NKG + k] = sc2;
    } else if (tid < 224) {                   // 8 rows x 20 aroma slots
        const int task = tid - 64;
        const int r = task / NKA, k = task % NKA;
        const int b = b0 + r;
        const int   idx = aromas[b * NKA + k];
        const float sc2 = aromas_scales[b * NKA + k];
        const float4* emb = reinterpret_cast<const float4*>(aroma_emb) + (size_t)idx * (NE / 4);
        const float4* yv4 = reinterpret_cast<const float4*>(&ya_sm[r * NE]);
        float acc = 0.f;
        #pragma unroll
        for (int i = 0; i < NE / 4; i++) {
            float4 ev = emb[i], yv = yv4[i];
            acc += ev.x * yv.x + ev.y * yv.y + ev.z * yv.z + ev.w * yv.w;
        }
        float mask = (sc2 != 0.f) ? 1.f : 0.f;
        out[(size_t)NB * 72 + (size_t)b * NKA + k] = sigmoidf_(acc) * mask;
        out[(size_t)NB * 92 + (size_t)b * NKA + k] = sc2;
    }
#undef REDUCE_Y
#undef FIN_HEADS
}

extern "C" void kernel_launch(void* const* d_in, const int* in_sizes, int n_in,
                              void* d_out, int out_size) {
    const float* x_enc          = (const float*)d_in[0];
    const int*   grapes         = (const int*)  d_in[1];
    const float* grapes_scales  = (const float*)d_in[2];
    const int*   aromas         = (const int*)  d_in[3];
    const float* aromas_scales  = (const float*)d_in[4];
    const float* W_common       = (const float*)d_in[5];
    const float* b_common       = (const float*)d_in[6];
    const float* W_country      = (const float*)d_in[7];
    const float* b_country      = (const float*)d_in[8];
    const float* W_type         = (const float*)d_in[9];
    const float* b_type         = (const float*)d_in[10];
    const float* W_taste        = (const float*)d_in[11];
    const float* b_taste        = (const float*)d_in[12];
    const float* W_aroma        = (const float*)d_in[13];
    const float* b_aroma        = (const float*)d_in[14];
    const float* W_grape        = (const float*)d_in[15];
    const float* b_grape        = (const float*)d_in[16];
    const float* grapes_emb     = (const float*)d_in[17];
    const float* aroma_emb      = (const float*)d_in[18];
    float* out = (float*)d_out;

    wine_fused<<<NB / 8, 256>>>(reinterpret_cast<const float4*>(x_enc),
                                grapes, grapes_scales, aromas, aromas_scales,
                                W_common, b_common, W_country, b_country,
                                W_type, b_type, W_taste, b_taste,
                                W_aroma, b_aroma, W_grape, b_grape,
                                grapes_emb, aroma_emb, out);
}